// round 1
// baseline (speedup 1.0000x reference)
#include <cuda_runtime.h>
#include <math.h>

#define B    8
#define CIN  512
#define COUT 256
#define H    64
#define W    64

// Scratch (static device globals; no runtime allocation)
__device__ float g_s[B * CIN];                       // modulation scalars [b][ci]
__device__ float g_w[B * 9 * CIN * COUT];            // weights [b][tap9][ci][co]
__device__ float g_mid[B * COUT * 129 * 132];        // convT output, row stride 132

// ---------------------------------------------------------------------------
// Kernel 1: s[b][ci] = style[b]·modW[ci]*1/sqrt(512) + bias[ci]
// ---------------------------------------------------------------------------
__global__ void k_style(const float* __restrict__ style,
                        const float* __restrict__ modw,
                        const float* __restrict__ modb) {
    int b = blockIdx.x;
    int ci = threadIdx.x;
    __shared__ __align__(16) float ss[CIN];
    ss[ci] = style[b * CIN + ci];
    __syncthreads();
    const float4* row = reinterpret_cast<const float4*>(modw + ci * CIN);
    const float4* s4p = reinterpret_cast<const float4*>(ss);
    float acc = 0.f;
#pragma unroll 4
    for (int k = 0; k < CIN / 4; k++) {
        float4 m = row[k];
        float4 s4 = s4p[k];
        acc += m.x * s4.x + m.y * s4.y + m.z * s4.z + m.w * s4.w;
    }
    g_s[b * CIN + ci] = acc * 0.044194173824159216f + modb[ci];
}

// ---------------------------------------------------------------------------
// Kernel 2: modulate + demodulate; write g_w[b][tap][ci][co]
// ---------------------------------------------------------------------------
__global__ void k_modw(const float* __restrict__ weight) {
    int co = blockIdx.x, b = blockIdx.y;
    __shared__ float tmp[CIN * 9];
    __shared__ float red[8];
    __shared__ float sdem;
    const float* wrow = weight + co * CIN * 9;
    const float* srow = g_s + b * CIN;
    float local = 0.f;
    for (int idx = threadIdx.x; idx < CIN * 9; idx += 256) {
        int ci = idx / 9;
        float t = 0.014731391274719739f * wrow[idx] * srow[ci];  // 1/sqrt(4608)
        tmp[idx] = t;
        local += t * t;
    }
#pragma unroll
    for (int o = 16; o; o >>= 1) local += __shfl_xor_sync(0xffffffffu, local, o);
    if ((threadIdx.x & 31) == 0) red[threadIdx.x >> 5] = local;
    __syncthreads();
    if (threadIdx.x == 0) {
        float s = 0.f;
#pragma unroll
        for (int i = 0; i < 8; i++) s += red[i];
        sdem = rsqrtf(s + 1e-8f);
    }
    __syncthreads();
    float demod = sdem;
    for (int idx = threadIdx.x; idx < CIN * 9; idx += 256) {
        int ci = idx / 9, tap = idx - ci * 9;
        g_w[((b * 9 + tap) * CIN + ci) * COUT + co] = tmp[idx] * demod;
    }
}

// ---------------------------------------------------------------------------
// Kernel 3: conv_transpose stride-2, decomposed by output parity (PY,PX).
// mid[2u+PY, 2v+PX] = sum_ci sum_taps x[u-dy, v-dx] * w[ky,kx]
//   PY==0: (ky,dy) in {(0,0),(2,1)};  PY==1: {(1,0)}   (same for x-dim)
// CTA: 64 cout x (4u x 32v) tile.  8 warps; warp -> 8 couts; lane -> v.
// ---------------------------------------------------------------------------
template <int PY, int PX>
__global__ void __launch_bounds__(256) k_convt(const float* __restrict__ x) {
    constexpr int NT_Y = (PY == 0) ? 2 : 1;
    constexpr int NT_X = (PX == 0) ? 2 : 1;
    constexpr int NTAPS = NT_Y * NT_X;
    constexpr int U = (PY == 0) ? 65 : 64;
    constexpr int V = (PX == 0) ? 65 : 64;
    constexpr int VT = (V + 31) / 32;

    __shared__ float xs[16][5][33];
    __shared__ float ws[16][NTAPS][64];

    int vt = blockIdx.x % VT, ut = blockIdx.x / VT;
    int v0 = vt * 32, u0 = ut * 4;
    int cobase = blockIdx.y * 64;
    int b = blockIdx.z;
    int tid = threadIdx.x;
    int lane = tid & 31, warp = tid >> 5;
    int wco = warp * 8;

    const int KYa[2] = {(PY == 0) ? 0 : 1, 2};
    const int KXa[2] = {(PX == 0) ? 0 : 1, 2};

    float acc[8][4];
#pragma unroll
    for (int i = 0; i < 8; i++)
#pragma unroll
        for (int j = 0; j < 4; j++) acc[i][j] = 0.f;

    const float* xb = x + b * CIN * H * W;

    for (int ci0 = 0; ci0 < CIN; ci0 += 16) {
        __syncthreads();
        // load input tile: rows u0-1..u0+3, cols v0-1..v0+31 (zero pad OOB)
        for (int e = tid; e < 16 * 5 * 33; e += 256) {
            int ci = e / 165;
            int rem = e - ci * 165;
            int r = rem / 33, c = rem - r * 33;
            int iy = u0 - 1 + r, ix = v0 - 1 + c;
            float v = 0.f;
            if (iy >= 0 && iy < H && ix >= 0 && ix < W)
                v = xb[((ci0 + ci) * H + iy) * W + ix];
            xs[ci][r][c] = v;
        }
        // load weight tile
        for (int e = tid; e < 16 * NTAPS * 64; e += 256) {
            int ci = e / (NTAPS * 64);
            int rem = e - ci * (NTAPS * 64);
            int t = rem / 64, co = rem - t * 64;
            int ty = t / NT_X, tx = t - ty * NT_X;
            int tap9 = KYa[ty] * 3 + KXa[tx];
            ws[ci][t][co] =
                g_w[((b * 9 + tap9) * CIN + ci0 + ci) * COUT + cobase + co];
        }
        __syncthreads();

#pragma unroll
        for (int kci = 0; kci < 16; kci++) {
#pragma unroll
            for (int tx = 0; tx < NT_X; tx++) {
                int dvx = (NT_X == 2) ? tx : 0;
                int cx = lane + 1 - dvx;
                float xr[5];
#pragma unroll
                for (int r = 0; r < 5; r++) xr[r] = xs[kci][r][cx];
#pragma unroll
                for (int ty = 0; ty < NT_Y; ty++) {
                    int t = ty * NT_X + tx;
                    int dy = (NT_Y == 2) ? ty : 0;
#pragma unroll
                    for (int i = 0; i < 8; i++) {
                        float wv = ws[kci][t][wco + i];
#pragma unroll
                        for (int j = 0; j < 4; j++)
                            acc[i][j] = fmaf(wv, xr[j + 1 - dy], acc[i][j]);
                    }
                }
            }
        }
    }

#pragma unroll
    for (int i = 0; i < 8; i++) {
        int co = cobase + wco + i;
#pragma unroll
        for (int j = 0; j < 4; j++) {
            int u = u0 + j, v = v0 + lane;
            if (u < U && v < V) {
                int my = 2 * u + PY, mx = 2 * v + PX;
                g_mid[((b * COUT + co) * 129 + my) * 132 + mx] = acc[i][j];
            }
        }
    }
}

// ---------------------------------------------------------------------------
// Kernel 4: 4x4 blur (separable [1,3,3,1]/4 each dim), pad 1: 129x129 -> 128x128
// ---------------------------------------------------------------------------
__global__ void k_blur(float* __restrict__ out) {
    int tx0 = blockIdx.x * 32, ty0 = blockIdx.y * 32;
    int bc = blockIdx.z;  // b*COUT + co
    __shared__ float ms[35][36];
    const float* mid = g_mid + bc * 129 * 132;
    for (int e = threadIdx.x; e < 35 * 35; e += 256) {
        int r = e / 35, c = e - r * 35;
        int my = ty0 - 1 + r, mx = tx0 - 1 + c;
        float v = 0.f;
        if (my >= 0 && my < 129 && mx >= 0 && mx < 129) v = mid[my * 132 + mx];
        ms[r][c] = v;
    }
    __syncthreads();
    int fx = threadIdx.x & 31;
    int q = (threadIdx.x >> 5) * 4;
    float cs[7];
#pragma unroll
    for (int m = 0; m < 7; m++) {
        float* row = ms[q + m];
        cs[m] = row[fx] + 3.f * row[fx + 1] + 3.f * row[fx + 2] + row[fx + 3];
    }
    float* op = out + (bc * 128 + ty0 + q) * 128 + tx0 + fx;
#pragma unroll
    for (int j = 0; j < 4; j++) {
        float s = cs[j] + 3.f * cs[j + 1] + 3.f * cs[j + 2] + cs[j + 3];
        op[j * 128] = s * (1.f / 16.f);
    }
}

// ---------------------------------------------------------------------------
extern "C" void kernel_launch(void* const* d_in, const int* in_sizes, int n_in,
                              void* d_out, int out_size) {
    const float* input  = (const float*)d_in[0];
    const float* style  = (const float*)d_in[1];
    const float* weight = (const float*)d_in[2];
    const float* modw   = (const float*)d_in[3];
    const float* modb   = (const float*)d_in[4];
    float* out = (float*)d_out;

    k_style<<<B, CIN>>>(style, modw, modb);
    k_modw<<<dim3(COUT, B), 256>>>(weight);
    k_convt<0, 0><<<dim3(17 * 3, 4, B), 256>>>(input);
    k_convt<0, 1><<<dim3(17 * 2, 4, B), 256>>>(input);
    k_convt<1, 0><<<dim3(16 * 3, 4, B), 256>>>(input);
    k_convt<1, 1><<<dim3(16 * 2, 4, B), 256>>>(input);
    k_blur<<<dim3(4, 4, B * COUT), 256>>>(out);
}

// round 6
// speedup vs baseline: 3.4240x; 3.4240x over previous
#include <cuda_runtime.h>
#include <math.h>

#define B    8
#define CIN  512
#define COUT 256
#define H    64
#define W    64

// Static device scratch (no runtime allocation)
__device__ float g_s[B * CIN];                 // modulation scalars s[b][ci]
__device__ float g_demod[B * COUT];            // demod[b][co]
__device__ float g_wt[9 * CIN * COUT];         // tf32(scale*weight) [tap9][ci][co]
__device__ float g_xs[B * CIN * H * W];        // tf32(x * s)        [b][ci][h][w]
__device__ float g_mid[B * COUT * 129 * 132];  // convT output, row stride 132

__device__ __forceinline__ float tf32r(float x) {
    unsigned u;
    asm("cvt.rna.tf32.f32 %0, %1;" : "=r"(u) : "f"(x));
    return __uint_as_float(u);
}

// ---------------------------------------------------------------------------
// Kernel 1: s[b][ci] = style[b]·modW[ci]/sqrt(512) + bias[ci]
// ---------------------------------------------------------------------------
__global__ void k_style(const float* __restrict__ style,
                        const float* __restrict__ modw,
                        const float* __restrict__ modb) {
    int b = blockIdx.x;
    int ci = threadIdx.x;
    __shared__ __align__(16) float ss[CIN];
    ss[ci] = style[b * CIN + ci];
    __syncthreads();
    const float4* row = reinterpret_cast<const float4*>(modw + ci * CIN);
    const float4* s4p = reinterpret_cast<const float4*>(ss);
    float acc = 0.f;
#pragma unroll 4
    for (int k = 0; k < CIN / 4; k++) {
        float4 m = row[k];
        float4 s4 = s4p[k];
        acc += m.x * s4.x + m.y * s4.y + m.z * s4.z + m.w * s4.w;
    }
    g_s[b * CIN + ci] = acc * 0.044194173824159216f + modb[ci];
}

// ---------------------------------------------------------------------------
// Kernel 2: g_wt[tap][ci][co] = tf32(scale * weight[co][ci][tap])
// ---------------------------------------------------------------------------
__global__ void k_wt(const float* __restrict__ weight) {
    int idx = blockIdx.x * 256 + threadIdx.x;  // (tap*512+ci)*256+co
    int co = idx & 255;
    int rem = idx >> 8;
    int ci = rem & 511;
    int tap = rem >> 9;
    float w = weight[(co * CIN + ci) * 9 + tap];
    g_wt[idx] = tf32r(0.014731391274719739f * w);  // 1/sqrt(4608)
}

// ---------------------------------------------------------------------------
// Kernel 3: g_xs = tf32(x * s[b][ci])   (float4 vectorized)
// ---------------------------------------------------------------------------
__global__ void k_xs(const float* __restrict__ x) {
    int idx = blockIdx.x * 256 + threadIdx.x;          // float4 index
    int bc = idx >> 10;                                // (b*CIN+ci): 4096/4 per ch
    float s = g_s[bc];
    float4 v = reinterpret_cast<const float4*>(x)[idx];
    float4 o;
    o.x = tf32r(v.x * s); o.y = tf32r(v.y * s);
    o.z = tf32r(v.z * s); o.w = tf32r(v.w * s);
    reinterpret_cast<float4*>(g_xs)[idx] = o;
}

// ---------------------------------------------------------------------------
// Kernel 4: demod[b][co] = rsqrt(scale^2 * sum_ci s^2 * sum_k w^2 + 1e-8)
// ---------------------------------------------------------------------------
__global__ void k_demod(const float* __restrict__ weight) {
    int co = blockIdx.x;
    int tid = threadIdx.x;
    __shared__ float sred[8][8];
    float part[B];
#pragma unroll
    for (int b = 0; b < B; b++) part[b] = 0.f;
    for (int cc = 0; cc < 2; cc++) {
        int ci = tid + cc * 256;
        float q = 0.f;
        const float* wr = weight + (co * CIN + ci) * 9;
#pragma unroll
        for (int k = 0; k < 9; k++) { float w = wr[k]; q += w * w; }
#pragma unroll
        for (int b = 0; b < B; b++) {
            float s = g_s[b * CIN + ci];
            part[b] += q * s * s;
        }
    }
#pragma unroll
    for (int b = 0; b < B; b++) {
#pragma unroll
        for (int o = 16; o; o >>= 1)
            part[b] += __shfl_xor_sync(0xffffffffu, part[b], o);
    }
    if ((tid & 31) == 0) {
#pragma unroll
        for (int b = 0; b < B; b++) sred[b][tid >> 5] = part[b];
    }
    __syncthreads();
    if (tid < B) {
        float s = 0.f;
#pragma unroll
        for (int w = 0; w < 8; w++) s += sred[tid][w];
        const float sc2 = 0.014731391274719739f * 0.014731391274719739f;
        g_demod[tid * COUT + co] = rsqrtf(sc2 * s + 1e-8f);
    }
}

// ---------------------------------------------------------------------------
// Kernel 5: conv_transpose stride-2 by parity, tf32 mma.sync GEMM.
// C[co, pix] = demod * sum_tap sum_ci Wt[tap][ci][co] * xs[ci][u-dy][v-dx]
// CTA: 128 co x 128 pixels (flattened u*V+v). 8 warps: warp_m(4) x warp_n(2).
// ---------------------------------------------------------------------------
#define SPAD 136  // 128 + 8 pad: (136*k) mod 32 = 8k -> conflict-free frag loads

template <int PY, int PX>
__global__ void __launch_bounds__(256, 2) k_convt_mma() {
    constexpr int NT_Y = (PY == 0) ? 2 : 1;
    constexpr int NT_X = (PX == 0) ? 2 : 1;
    constexpr int U = (PY == 0) ? 65 : 64;
    constexpr int V = (PX == 0) ? 65 : 64;
    constexpr int NPIX = U * V;

    __shared__ float as_[32 * SPAD];
    __shared__ float bs[32 * SPAD];
    __shared__ int us[128], vs[128];

    const int tid = threadIdx.x;
    const int n0 = blockIdx.x * 128;
    const int cobase = blockIdx.y * 128;
    const int b = blockIdx.z;

    if (tid < 128) {
        int p = n0 + tid;
        int u = p / V;
        int v = p - u * V;
        us[tid] = (p < NPIX) ? u : -1000;
        vs[tid] = v;
    }

    const int lane = tid & 31;
    const int g = lane >> 2, tg = lane & 3;
    const int warp = tid >> 5;
    const int wm = warp >> 1, wn = warp & 1;

    float acc[2][8][4];
#pragma unroll
    for (int mi = 0; mi < 2; mi++)
#pragma unroll
        for (int nt = 0; nt < 8; nt++)
#pragma unroll
            for (int r = 0; r < 4; r++) acc[mi][nt][r] = 0.f;

    const float* xb = g_xs + b * CIN * H * W;
    const unsigned* asu = reinterpret_cast<const unsigned*>(as_);
    const unsigned* bsu = reinterpret_cast<const unsigned*>(bs);

    const int jB = tid & 127;        // pixel column this thread stages
    const int kcB = tid >> 7;        // 0/1

#pragma unroll 1
    for (int t = 0; t < NT_Y * NT_X; t++) {
        const int ty = t / NT_X, tx = t - ty * NT_X;
        const int ky = (PY == 0) ? (ty ? 2 : 0) : 1;
        const int kx = (PX == 0) ? (tx ? 2 : 0) : 1;
        const int dy = (PY == 0) ? ty : 0;
        const int dx = (PX == 0) ? tx : 0;
        const int tap9 = ky * 3 + kx;
        const float* wtap = g_wt + tap9 * CIN * COUT;

#pragma unroll 1
        for (int ci0 = 0; ci0 < CIN; ci0 += 32) {
            __syncthreads();
            // Stage A: Wt[ci0..+32][cobase..+128] -> as_[kc][co], float4
#pragma unroll
            for (int k = 0; k < 4; k++) {
                int vi = tid + k * 256;
                int kc = vi >> 5, c4 = vi & 31;
                float4 w4 = *reinterpret_cast<const float4*>(
                    wtap + (ci0 + kc) * COUT + cobase + c4 * 4);
                *reinterpret_cast<float4*>(as_ + kc * SPAD + c4 * 4) = w4;
            }
            // Stage B: xs[ci0+kc][u-dy][v-dx] -> bs[kc][j]
            {
                int u = us[jB], v = vs[jB];
                int y = u - dy, x = v - dx;
                bool ok = (y >= 0) && (y < H) && (x >= 0) && (x < W);
                int off = (y << 6) + x;
#pragma unroll
                for (int i = 0; i < 16; i++) {
                    int kc = kcB + i * 2;
                    float val = ok ? xb[((ci0 + kc) << 12) + off] : 0.f;
                    bs[kc * SPAD + jB] = val;
                }
            }
            __syncthreads();

#pragma unroll
            for (int ks = 0; ks < 4; ks++) {
                const int k0 = ks * 8;
                unsigned a[2][4], bb[8][2];
                const unsigned* ar0 = asu + (k0 + tg) * SPAD + wm * 32 + g;
                const unsigned* ar1 = asu + (k0 + tg + 4) * SPAD + wm * 32 + g;
#pragma unroll
                for (int mi = 0; mi < 2; mi++) {
                    a[mi][0] = ar0[mi * 16];
                    a[mi][1] = ar0[mi * 16 + 8];
                    a[mi][2] = ar1[mi * 16];
                    a[mi][3] = ar1[mi * 16 + 8];
                }
                const unsigned* br0 = bsu + (k0 + tg) * SPAD + wn * 64 + g;
                const unsigned* br1 = bsu + (k0 + tg + 4) * SPAD + wn * 64 + g;
#pragma unroll
                for (int nt = 0; nt < 8; nt++) {
                    bb[nt][0] = br0[nt * 8];
                    bb[nt][1] = br1[nt * 8];
                }
#pragma unroll
                for (int mi = 0; mi < 2; mi++)
#pragma unroll
                    for (int nt = 0; nt < 8; nt++) {
                        asm volatile(
                            "mma.sync.aligned.m16n8k8.row.col.f32.tf32.tf32.f32 "
                            "{%0,%1,%2,%3}, {%4,%5,%6,%7}, {%8,%9}, {%0,%1,%2,%3};"
                            : "+f"(acc[mi][nt][0]), "+f"(acc[mi][nt][1]),
                              "+f"(acc[mi][nt][2]), "+f"(acc[mi][nt][3])
                            : "r"(a[mi][0]), "r"(a[mi][1]), "r"(a[mi][2]),
                              "r"(a[mi][3]), "r"(bb[nt][0]), "r"(bb[nt][1]));
                    }
            }
        }
    }

    // Epilogue: scale by demod, scatter into g_mid at (2u+PY, 2v+PX)
#pragma unroll
    for (int mi = 0; mi < 2; mi++) {
        int r0 = cobase + wm * 32 + mi * 16 + g;
        float d0 = g_demod[b * COUT + r0];
        float d1 = g_demod[b * COUT + r0 + 8];
        float* m0 = g_mid + (b * COUT + r0) * 129 * 132;
        float* m1 = g_mid + (b * COUT + r0 + 8) * 129 * 132;
#pragma unroll
        for (int nt = 0; nt < 8; nt++) {
            int px = wn * 64 + nt * 8 + tg * 2;
#pragma unroll
            for (int c = 0; c < 2; c++) {
                int j = px + c;
                int u = us[j];
                if (u < 0) continue;
                int v = vs[j];
                int off = (2 * u + PY) * 132 + 2 * v + PX;
                m0[off] = acc[mi][nt][c] * d0;
                m1[off] = acc[mi][nt][2 + c] * d1;
            }
        }
    }
}

// ---------------------------------------------------------------------------
// Kernel 6: 4x4 blur (separable [1,3,3,1]), pad 1: 129x129 -> 128x128
// ---------------------------------------------------------------------------
__global__ void k_blur(float* __restrict__ out) {
    int tx0 = blockIdx.x * 32, ty0 = blockIdx.y * 32;
    int bc = blockIdx.z;
    __shared__ float ms[35][36];
    const float* mid = g_mid + bc * 129 * 132;
    for (int e = threadIdx.x; e < 35 * 35; e += 256) {
        int r = e / 35, c = e - r * 35;
        int my = ty0 - 1 + r, mx = tx0 - 1 + c;
        float v = 0.f;
        if (my >= 0 && my < 129 && mx >= 0 && mx < 129) v = mid[my * 132 + mx];
        ms[r][c] = v;
    }
    __syncthreads();
    int fx = threadIdx.x & 31;
    int q = (threadIdx.x >> 5) * 4;
    float cs[7];
#pragma unroll
    for (int m = 0; m < 7; m++) {
        float* row = ms[q + m];
        cs[m] = row[fx] + 3.f * row[fx + 1] + 3.f * row[fx + 2] + row[fx + 3];
    }
    float* op = out + (bc * 128 + ty0 + q) * 128 + tx0 + fx;
#pragma unroll
    for (int j = 0; j < 4; j++) {
        float s = cs[j] + 3.f * cs[j + 1] + 3.f * cs[j + 2] + cs[j + 3];
        op[j * 128] = s * (1.f / 16.f);
    }
}

// ---------------------------------------------------------------------------
extern "C" void kernel_launch(void* const* d_in, const int* in_sizes, int n_in,
                              void* d_out, int out_size) {
    const float* input  = (const float*)d_in[0];
    const float* style  = (const float*)d_in[1];
    const float* weight = (const float*)d_in[2];
    const float* modw   = (const float*)d_in[3];
    const float* modb   = (const float*)d_in[4];
    float* out = (float*)d_out;

    k_style<<<B, CIN>>>(style, modw, modb);
    k_wt<<<9 * CIN * COUT / 256, 256>>>(weight);
    k_xs<<<(B * CIN * H * W / 4) / 256, 256>>>(input);
    k_demod<<<COUT, 256>>>(weight);

    k_convt_mma<0, 0><<<dim3(34, 2, B), 256>>>();  // 65*65 px, 4 taps
    k_convt_mma<0, 1><<<dim3(33, 2, B), 256>>>();  // 65*64 px, 2 taps
    k_convt_mma<1, 0><<<dim3(33, 2, B), 256>>>();  // 64*65 px, 2 taps
    k_convt_mma<1, 1><<<dim3(32, 2, B), 256>>>();  // 64*64 px, 1 tap

    k_blur<<<dim3(4, 4, B * COUT), 256>>>(out);
}

// round 8
// speedup vs baseline: 6.4335x; 1.8789x over previous
#include <cuda_runtime.h>
#include <cuda_fp16.h>
#include <math.h>
#include <stdint.h>

#define B    8
#define CIN  512
#define COUT 256
#define H    64
#define W    64

// ---------------- static device scratch ----------------
__device__ float  g_s[B * CIN];                  // modulation scalars s[b][ci]
__device__ float  g_demod[B * COUT];             // demod[b][co]
__device__ __half g_wtT[9 * COUT * CIN];         // half(scale*w) [tap][co][ci]
__device__ __half g_xsT[B * H * W * CIN];        // half(x*s)     [b][y][x][ci]
__device__ float  g_midp[4][B * COUT * 65 * 68]; // parity planes [py*2+px]

__device__ __forceinline__ uint32_t smem_u32(const void* p) {
    uint32_t a;
    asm("{ .reg .u64 t; cvta.to.shared.u64 t, %1; cvt.u32.u64 %0, t; }"
        : "=r"(a) : "l"(p));
    return a;
}
__device__ __forceinline__ uint32_t sw128(uint32_t o) { return o ^ ((o >> 3) & 0x70); }

#define CP_ASYNC(dst, src, sz) \
    asm volatile("cp.async.cg.shared.global [%0], [%1], 16, %2;" \
                 :: "r"(dst), "l"(src), "r"(sz) : "memory")
#define CP_COMMIT() asm volatile("cp.async.commit_group;" ::: "memory")
#define CP_WAIT1()  asm volatile("cp.async.wait_group 1;" ::: "memory")
#define CP_WAIT0()  asm volatile("cp.async.wait_group 0;" ::: "memory")

// ---------------------------------------------------------------------------
// Kernel 1: s[b][ci] = style[b]·modW[ci]/sqrt(512) + bias[ci]
// ---------------------------------------------------------------------------
__global__ void k_style(const float* __restrict__ style,
                        const float* __restrict__ modw,
                        const float* __restrict__ modb) {
    int b = blockIdx.x;
    int ci = threadIdx.x;
    __shared__ __align__(16) float ss[CIN];
    ss[ci] = style[b * CIN + ci];
    __syncthreads();
    const float4* row = reinterpret_cast<const float4*>(modw + ci * CIN);
    const float4* s4p = reinterpret_cast<const float4*>(ss);
    float acc = 0.f;
#pragma unroll 4
    for (int k = 0; k < CIN / 4; k++) {
        float4 m = row[k];
        float4 s4 = s4p[k];
        acc += m.x * s4.x + m.y * s4.y + m.z * s4.z + m.w * s4.w;
    }
    g_s[b * CIN + ci] = acc * 0.044194173824159216f + modb[ci];
}

// ---------------------------------------------------------------------------
// Kernel 2: g_wtT[tap][co][ci] = half(scale * weight[co][ci][tap])
// ---------------------------------------------------------------------------
__global__ void k_wtT(const float* __restrict__ weight) {
    int co = blockIdx.x;
    __shared__ float sw[CIN * 9];
    for (int e = threadIdx.x; e < CIN * 9; e += 256) sw[e] = weight[co * CIN * 9 + e];
    __syncthreads();
    for (int e = threadIdx.x; e < CIN * 9; e += 256) {
        int tap = e >> 9, ci = e & 511;
        g_wtT[(tap * COUT + co) * CIN + ci] =
            __float2half_rn(0.014731391274719739f * sw[ci * 9 + tap]);
    }
}

// ---------------------------------------------------------------------------
// Kernel 3: g_xsT[b][y][x][ci] = half(x[b][ci][y][x] * s[b][ci])
// ---------------------------------------------------------------------------
__global__ void k_xsT(const float* __restrict__ x) {
    int y = blockIdx.x, b = blockIdx.y;
    __shared__ float t[32][65];
    const float* xb = x + (size_t)b * CIN * H * W + y * W;
    __half* ob = g_xsT + ((size_t)(b * H + y) * W) * CIN;
    for (int ci0 = 0; ci0 < CIN; ci0 += 32) {
        __syncthreads();
#pragma unroll
        for (int k = 0; k < 8; k++) {
            int e = threadIdx.x + k * 256;
            int ci = e >> 6, xc = e & 63;
            float s = g_s[b * CIN + ci0 + ci];
            t[ci][xc] = xb[(ci0 + ci) * H * W + xc] * s;
        }
        __syncthreads();
#pragma unroll
        for (int k = 0; k < 4; k++) {
            int e = threadIdx.x + k * 256;
            int xc = e >> 4, cp = e & 15;
            __half2 h = __floats2half2_rn(t[cp * 2][xc], t[cp * 2 + 1][xc]);
            *(reinterpret_cast<__half2*>(ob + xc * CIN + ci0) + cp) = h;
        }
    }
}

// ---------------------------------------------------------------------------
// Kernel 4: demod[b][co] (exact fp32, matches reference)
// ---------------------------------------------------------------------------
__global__ void k_demod(const float* __restrict__ weight) {
    int co = blockIdx.x;
    int tid = threadIdx.x;
    __shared__ float sred[8][8];
    float part[B];
#pragma unroll
    for (int b = 0; b < B; b++) part[b] = 0.f;
    for (int cc = 0; cc < 2; cc++) {
        int ci = tid + cc * 256;
        float q = 0.f;
        const float* wr = weight + (co * CIN + ci) * 9;
#pragma unroll
        for (int k = 0; k < 9; k++) { float w = wr[k]; q += w * w; }
#pragma unroll
        for (int b = 0; b < B; b++) {
            float s = g_s[b * CIN + ci];
            part[b] += q * s * s;
        }
    }
#pragma unroll
    for (int b = 0; b < B; b++) {
#pragma unroll
        for (int o = 16; o; o >>= 1)
            part[b] += __shfl_xor_sync(0xffffffffu, part[b], o);
    }
    if ((tid & 31) == 0) {
#pragma unroll
        for (int b = 0; b < B; b++) sred[b][tid >> 5] = part[b];
    }
    __syncthreads();
    if (tid < B) {
        float s = 0.f;
#pragma unroll
        for (int w = 0; w < 8; w++) s += sred[tid][w];
        const float sc2 = 0.014731391274719739f * 0.014731391274719739f;
        g_demod[tid * COUT + co] = rsqrtf(sc2 * s + 1e-8f);
    }
}

// ---------------------------------------------------------------------------
// Kernel 5: conv_transpose by parity, fp16 mma.sync m16n8k16 GEMM.
// C[128co, 128px] = sum_{tap,ci} WtT[tap][co][ci] * xsT[y-dy][x-dx][ci]
// K-chunk = 64 ci (128B half rows, SW128). cp.async double buffered.
// smem: us 512 | vs 512 | A0 16K | A1 16K | B0 16K | B1 16K  = 67584 B
// ---------------------------------------------------------------------------
#define SM_US   0
#define SM_VS   512
#define SM_A0   2048
#define SM_A1   18432
#define SM_B0   34816
#define SM_B1   51200
#define SM_DYN  67584

template <int PY, int PX>
__global__ void __launch_bounds__(256, 2) k_conv() {
    constexpr int NT_Y = (PY == 0) ? 2 : 1;
    constexpr int NT_X = (PX == 0) ? 2 : 1;
    constexpr int U = (PY == 0) ? 65 : 64;
    constexpr int V = (PX == 0) ? 65 : 64;
    constexpr int NPIX = U * V;
    constexpr int NC = NT_Y * NT_X * 8;  // chunks of 64 ci

    extern __shared__ __align__(1024) char smem[];
    const uint32_t sb = smem_u32(smem);
    int* us = (int*)(smem + SM_US);
    int* vs = (int*)(smem + SM_VS);

    const int tid = threadIdx.x;
    const int lane = tid & 31, warp = tid >> 5;
    const int g = lane >> 2, tg = lane & 3;
    const int wm = warp >> 1, wn = warp & 1;
    const int n0 = blockIdx.x * 128;
    const int cobase = blockIdx.y * 128;
    const int b = blockIdx.z;

    if (tid < 128) {
        int p = n0 + tid;
        int u = p / V, v = p - u * V;
        us[tid] = (p < NPIX) ? u : -1000;
        vs[tid] = v;
    }
    __syncthreads();

    const uint32_t Aoff[2] = {sb + SM_A0, sb + SM_A1};
    const uint32_t Boff[2] = {sb + SM_B0, sb + SM_B1};

    // issue chunk gidx into buffer gidx&1
    auto issue = [&](int gidx) {
        const int t = gidx >> 3;
        const int ci0 = (gidx & 7) * 64;
        const int ty = t / NT_X, tx = t - ty * NT_X;
        const int ky = (PY == 0) ? (ty ? 2 : 0) : 1;
        const int kx = (PX == 0) ? (tx ? 2 : 0) : 1;
        const int dy = (PY == 0) ? ty : 0;
        const int dx = (PX == 0) ? tx : 0;
        const uint32_t Ab = Aoff[gidx & 1], Bb = Boff[gidx & 1];
        const __half* wt = g_wtT + (ky * 3 + kx) * COUT * CIN + ci0;
        const __half* xt = g_xsT + ci0;
#pragma unroll
        for (int k = 0; k < 4; k++) {
            int f = tid + k * 256;
            int co = f >> 3, q = f & 7;
            const __half* src = wt + (size_t)(cobase + co) * CIN + q * 8;
            CP_ASYNC(Ab + sw128(co * 128 + q * 16), src, 16);
        }
#pragma unroll
        for (int k = 0; k < 4; k++) {
            int f = tid + k * 256;
            int j = f >> 3, q = f & 7;
            int y = us[j] - dy, xx = vs[j] - dx;
            bool ok = (y >= 0) && (y < H) && (xx >= 0) && (xx < W);
            int yc = ok ? y : 0, xc = ok ? xx : 0;
            const __half* src = xt + (size_t)((b * H + yc) * W + xc) * CIN + q * 8;
            CP_ASYNC(Bb + sw128(j * 128 + q * 16), src, ok ? 16 : 0);
        }
        CP_COMMIT();
    };

    float acc[2][8][4];
#pragma unroll
    for (int mi = 0; mi < 2; mi++)
#pragma unroll
        for (int nt = 0; nt < 8; nt++)
#pragma unroll
            for (int r = 0; r < 4; r++) acc[mi][nt][r] = 0.f;

    issue(0);
    issue(1);

    // ldmatrix lane addressing (constant per thread)
    const int arow = wm * 32 + (lane & 15);          // + mi*16
    const int acolb = (lane >> 4) * 16;              // + ks*32
    const int brow = wn * 64 + ((lane >> 4) << 3) + (lane & 7);  // + ntp*16
    const int bcolb = ((lane >> 3) & 1) * 16;        // + ks*32

#pragma unroll 1
    for (int c = 0; c < NC; c++) {
        if (c < NC - 1) { CP_WAIT1(); } else { CP_WAIT0(); }
        __syncthreads();
        const uint32_t Ab = Aoff[c & 1], Bb = Boff[c & 1];
#pragma unroll
        for (int ks = 0; ks < 4; ks++) {
            uint32_t a[2][4], bb[8][2];
#pragma unroll
            for (int mi = 0; mi < 2; mi++) {
                uint32_t addr = Ab + sw128((arow + mi * 16) * 128 + acolb + ks * 32);
                asm volatile(
                    "ldmatrix.sync.aligned.m8n8.x4.shared.b16 {%0,%1,%2,%3}, [%4];"
                    : "=r"(a[mi][0]), "=r"(a[mi][1]), "=r"(a[mi][2]), "=r"(a[mi][3])
                    : "r"(addr) : "memory");
            }
#pragma unroll
            for (int ntp = 0; ntp < 4; ntp++) {
                uint32_t addr = Bb + sw128((brow + ntp * 16) * 128 + bcolb + ks * 32);
                uint32_t r0, r1, r2, r3;
                asm volatile(
                    "ldmatrix.sync.aligned.m8n8.x4.shared.b16 {%0,%1,%2,%3}, [%4];"
                    : "=r"(r0), "=r"(r1), "=r"(r2), "=r"(r3)
                    : "r"(addr) : "memory");
                bb[ntp * 2][0] = r0;     bb[ntp * 2][1] = r1;
                bb[ntp * 2 + 1][0] = r2; bb[ntp * 2 + 1][1] = r3;
            }
#pragma unroll
            for (int mi = 0; mi < 2; mi++)
#pragma unroll
                for (int nt = 0; nt < 8; nt++) {
                    asm volatile(
                        "mma.sync.aligned.m16n8k16.row.col.f32.f16.f16.f32 "
                        "{%0,%1,%2,%3}, {%4,%5,%6,%7}, {%8,%9}, {%0,%1,%2,%3};"
                        : "+f"(acc[mi][nt][0]), "+f"(acc[mi][nt][1]),
                          "+f"(acc[mi][nt][2]), "+f"(acc[mi][nt][3])
                        : "r"(a[mi][0]), "r"(a[mi][1]), "r"(a[mi][2]),
                          "r"(a[mi][3]), "r"(bb[nt][0]), "r"(bb[nt][1]));
                }
        }
        __syncthreads();
        if (c + 2 < NC) issue(c + 2);
    }

    // Epilogue: demod scale + scatter to parity plane
    float* plane = g_midp[PY * 2 + PX];
#pragma unroll
    for (int mi = 0; mi < 2; mi++) {
        int r0 = cobase + wm * 32 + mi * 16 + g;
        float d0 = g_demod[b * COUT + r0];
        float d1 = g_demod[b * COUT + r0 + 8];
        float* p0 = plane + ((size_t)(b * COUT + r0) * 65) * 68;
        float* p1 = plane + ((size_t)(b * COUT + r0 + 8) * 65) * 68;
#pragma unroll
        for (int nt = 0; nt < 8; nt++) {
            int px = wn * 64 + nt * 8 + tg * 2;
#pragma unroll
            for (int cc = 0; cc < 2; cc++) {
                int j = px + cc;
                int u = us[j];
                if (u < 0) continue;
                int v = vs[j];
                p0[u * 68 + v] = acc[mi][nt][cc] * d0;
                p1[u * 68 + v] = acc[mi][nt][2 + cc] * d1;
            }
        }
    }
}

// ---------------------------------------------------------------------------
// Kernel 6: 4x4 blur from parity planes -> out [B,COUT,128,128]
// ---------------------------------------------------------------------------
__global__ void k_blur(float* __restrict__ out) {
    int tx0 = blockIdx.x * 32, ty0 = blockIdx.y * 32;
    int bc = blockIdx.z;
    __shared__ float ms[35][36];
    for (int e = threadIdx.x; e < 35 * 35; e += 256) {
        int r = e / 35, c = e - r * 35;
        int my = ty0 - 1 + r, mx = tx0 - 1 + c;
        float v = 0.f;
        if (my >= 0 && my < 129 && mx >= 0 && mx < 129)
            v = g_midp[(my & 1) * 2 + (mx & 1)]
                      [((size_t)bc * 65 + (my >> 1)) * 68 + (mx >> 1)];
        ms[r][c] = v;
    }
    __syncthreads();
    int fx = threadIdx.x & 31;
    int q = (threadIdx.x >> 5) * 4;
    float cs[7];
#pragma unroll
    for (int m = 0; m < 7; m++) {
        float* row = ms[q + m];
        cs[m] = row[fx] + 3.f * row[fx + 1] + 3.f * row[fx + 2] + row[fx + 3];
    }
    float* op = out + ((size_t)bc * 128 + ty0 + q) * 128 + tx0 + fx;
#pragma unroll
    for (int j = 0; j < 4; j++) {
        float s = cs[j] + 3.f * cs[j + 1] + 3.f * cs[j + 2] + cs[j + 3];
        op[j * 128] = s * (1.f / 16.f);
    }
}

// ---------------------------------------------------------------------------
extern "C" void kernel_launch(void* const* d_in, const int* in_sizes, int n_in,
                              void* d_out, int out_size) {
    const float* input  = (const float*)d_in[0];
    const float* style  = (const float*)d_in[1];
    const float* weight = (const float*)d_in[2];
    const float* modw   = (const float*)d_in[3];
    const float* modb   = (const float*)d_in[4];
    float* out = (float*)d_out;

    cudaFuncSetAttribute(k_conv<0, 0>, cudaFuncAttributeMaxDynamicSharedMemorySize, SM_DYN);
    cudaFuncSetAttribute(k_conv<0, 1>, cudaFuncAttributeMaxDynamicSharedMemorySize, SM_DYN);
    cudaFuncSetAttribute(k_conv<1, 0>, cudaFuncAttributeMaxDynamicSharedMemorySize, SM_DYN);
    cudaFuncSetAttribute(k_conv<1, 1>, cudaFuncAttributeMaxDynamicSharedMemorySize, SM_DYN);

    k_style<<<B, CIN>>>(style, modw, modb);
    k_wtT<<<COUT, 256>>>(weight);
    k_xsT<<<dim3(H, B), 256>>>(input);
    k_demod<<<COUT, 256>>>(weight);

    k_conv<0, 0><<<dim3(34, 2, B), 256, SM_DYN>>>();  // 65*65 px, 4 taps
    k_conv<0, 1><<<dim3(33, 2, B), 256, SM_DYN>>>();  // 65*64 px, 2 taps
    k_conv<1, 0><<<dim3(33, 2, B), 256, SM_DYN>>>();  // 64*65 px, 2 taps
    k_conv<1, 1><<<dim3(32, 2, B), 256, SM_DYN>>>();  // 64*64 px, 1 tap

    k_blur<<<dim3(4, 4, B * COUT), 256>>>(out);
}

// round 11
// speedup vs baseline: 7.0536x; 1.0964x over previous
#include <cuda_runtime.h>
#include <cuda_fp16.h>
#include <math.h>
#include <stdint.h>

#define B    8
#define CIN  512
#define COUT 256
#define H    64
#define W    64

// ---------------- static device scratch (16B-aligned for cp.async) ----------
__device__ __align__(16) float  g_s[B * CIN];
__device__ __align__(16) float  g_demod[B * COUT];
__device__ __align__(16) __half g_wtT[9 * COUT * CIN];      // [tap][co][ci]
__device__ __align__(16) __half g_xsT[B * 66 * 66 * CIN];   // zero halo [b][y+1][x+1][ci]
__device__ __align__(16) __half g_midp[4][B * COUT * 65 * 68];  // parity planes

__device__ __forceinline__ uint32_t smem_u32(const void* p) {
    uint32_t a;
    asm("{ .reg .u64 t; cvta.to.shared.u64 t, %1; cvt.u32.u64 %0, t; }"
        : "=r"(a) : "l"(p));
    return a;
}
__device__ __forceinline__ uint32_t sw128(uint32_t o) { return o ^ ((o >> 3) & 0x70); }

#define CP_ASYNC16(dst, src) \
    asm volatile("cp.async.cg.shared.global [%0], [%1], 16;" \
                 :: "r"(dst), "l"(src) : "memory")
#define CP_COMMIT() asm volatile("cp.async.commit_group;" ::: "memory")
#define CP_WAIT1()  asm volatile("cp.async.wait_group 1;" ::: "memory")
#define CP_WAIT0()  asm volatile("cp.async.wait_group 0;" ::: "memory")

// ---------------------------------------------------------------------------
// Kernel 1: s[b][ci] = style[b]·modW[ci]/sqrt(512) + bias[ci]
// ---------------------------------------------------------------------------
__global__ void k_style(const float* __restrict__ style,
                        const float* __restrict__ modw,
                        const float* __restrict__ modb) {
    int b = blockIdx.x;
    int ci = threadIdx.x;
    __shared__ __align__(16) float ss[CIN];
    ss[ci] = style[b * CIN + ci];
    __syncthreads();
    const float4* row = reinterpret_cast<const float4*>(modw + ci * CIN);
    const float4* s4p = reinterpret_cast<const float4*>(ss);
    float acc = 0.f;
#pragma unroll 4
    for (int k = 0; k < CIN / 4; k++) {
        float4 m = row[k];
        float4 s4 = s4p[k];
        acc += m.x * s4.x + m.y * s4.y + m.z * s4.z + m.w * s4.w;
    }
    g_s[b * CIN + ci] = acc * 0.044194173824159216f + modb[ci];
}

// ---------------------------------------------------------------------------
// Kernel 2: g_wtT[tap][co][ci] = half(scale * weight[co][ci][tap])
// ---------------------------------------------------------------------------
__global__ void k_wtT(const float* __restrict__ weight) {
    int co = blockIdx.x;
    __shared__ float sw[CIN * 9];
    for (int e = threadIdx.x; e < CIN * 9; e += 256) sw[e] = weight[co * CIN * 9 + e];
    __syncthreads();
    for (int e = threadIdx.x; e < CIN * 9; e += 256) {
        int tap = e >> 9, ci = e & 511;
        g_wtT[(tap * COUT + co) * CIN + ci] =
            __float2half_rn(0.014731391274719739f * sw[ci * 9 + tap]);
    }
}

// ---------------------------------------------------------------------------
// Kernel 3a: zero the halo of g_xsT (y1 in {0,65} or x1 in {0,65})
// ---------------------------------------------------------------------------
__global__ void k_halo() {
    int b = blockIdx.y;
    int idx = blockIdx.x * 256 + threadIdx.x;   // half2 units
    int px = idx >> 8, cp = idx & 255;          // 256 half2 per pixel
    if (px >= 260) return;
    int y1, x1;
    if (px < 66)       { y1 = 0;  x1 = px; }
    else if (px < 132) { y1 = 65; x1 = px - 66; }
    else if (px < 196) { y1 = px - 132 + 1; x1 = 0; }
    else               { y1 = px - 196 + 1; x1 = 65; }
    reinterpret_cast<__half2*>(
        g_xsT + ((size_t)(b * 66 + y1) * 66 + x1) * CIN)[cp] =
        __floats2half2_rn(0.f, 0.f);
}

// ---------------------------------------------------------------------------
// Kernel 3b: g_xsT[b][y+1][x+1][ci] = half(x[b][ci][y][x] * s[b][ci])
// ---------------------------------------------------------------------------
__global__ void k_xsT(const float* __restrict__ x) {
    int y = blockIdx.x, b = blockIdx.y;
    __shared__ float t[32][65];
    const float* xb = x + (size_t)b * CIN * H * W + y * W;
    __half* ob = g_xsT + ((size_t)(b * 66 + y + 1) * 66 + 1) * CIN;
    for (int ci0 = 0; ci0 < CIN; ci0 += 32) {
        __syncthreads();
#pragma unroll
        for (int k = 0; k < 8; k++) {
            int e = threadIdx.x + k * 256;
            int ci = e >> 6, xc = e & 63;
            float s = g_s[b * CIN + ci0 + ci];
            t[ci][xc] = xb[(ci0 + ci) * H * W + xc] * s;
        }
        __syncthreads();
#pragma unroll
        for (int k = 0; k < 4; k++) {
            int e = threadIdx.x + k * 256;
            int xc = e >> 4, cp = e & 15;
            __half2 h = __floats2half2_rn(t[cp * 2][xc], t[cp * 2 + 1][xc]);
            *(reinterpret_cast<__half2*>(ob + (size_t)xc * CIN + ci0) + cp) = h;
        }
    }
}

// ---------------------------------------------------------------------------
// Kernel 4: demod[b][co] (exact fp32)
// ---------------------------------------------------------------------------
__global__ void k_demod(const float* __restrict__ weight) {
    int co = blockIdx.x;
    int tid = threadIdx.x;
    __shared__ float sred[8][8];
    float part[B];
#pragma unroll
    for (int b = 0; b < B; b++) part[b] = 0.f;
    for (int cc = 0; cc < 2; cc++) {
        int ci = tid + cc * 256;
        float q = 0.f;
        const float* wr = weight + (co * CIN + ci) * 9;
#pragma unroll
        for (int k = 0; k < 9; k++) { float w = wr[k]; q += w * w; }
#pragma unroll
        for (int b = 0; b < B; b++) {
            float s = g_s[b * CIN + ci];
            part[b] += q * s * s;
        }
    }
#pragma unroll
    for (int b = 0; b < B; b++) {
#pragma unroll
        for (int o = 16; o; o >>= 1)
            part[b] += __shfl_xor_sync(0xffffffffu, part[b], o);
    }
    if ((tid & 31) == 0) {
#pragma unroll
        for (int b = 0; b < B; b++) sred[b][tid >> 5] = part[b];
    }
    __syncthreads();
    if (tid < B) {
        float s = 0.f;
#pragma unroll
        for (int w = 0; w < 8; w++) s += sred[tid][w];
        const float sc2 = 0.014731391274719739f * 0.014731391274719739f;
        g_demod[tid * COUT + co] = rsqrtf(sc2 * s + 1e-8f);
    }
}

// ---------------------------------------------------------------------------
// Kernel 5: all four parities in ONE launch. fp16 mma.sync m16n8k16 GEMM.
// grid.x: [0,34) P00 | [34,67) P01 | [67,100) P10 | [100,132) P11
// 3-stage cp.async pipeline, one __syncthreads per 64-ci chunk.
// smem: us 512 | vs 512 | ue 512 | pad | 3 x (A 16K + B 16K) = 100352 B
// ---------------------------------------------------------------------------
#define SM_US   0
#define SM_VS   512
#define SM_UE   1024
#define SM_BUF  2048
#define SM_DYN  100352

__global__ void __launch_bounds__(256, 2) k_conv() {
    extern __shared__ __align__(1024) char smem[];
    const uint32_t sb = smem_u32(smem);
    int* us = (int*)(smem + SM_US);
    int* vs = (int*)(smem + SM_VS);
    int* ue = (int*)(smem + SM_UE);

    const int tid = threadIdx.x;
    const int lane = tid & 31, warp = tid >> 5;
    const int g = lane >> 2, tg = lane & 3;
    const int wm = warp >> 1, wn = warp & 1;
    const int cobase = blockIdx.y * 128;
    const int b = blockIdx.z;

    // parity decode
    int bx = blockIdx.x;
    int py, px, xt;
    if (bx < 34)       { py = 0; px = 0; xt = bx; }
    else if (bx < 67)  { py = 0; px = 1; xt = bx - 34; }
    else if (bx < 100) { py = 1; px = 0; xt = bx - 67; }
    else               { py = 1; px = 1; xt = bx - 100; }
    const int U = 65 - py, V = 65 - px;
    const int NPIX = U * V;
    const int nky = 2 - py, nkx = 2 - px;
    const int NC = nky * nkx * 8;
    const int n0 = xt * 128;

    {
        int p = n0 + tid;
        int u = p / V, v = p - u * V;
        bool ok = (p < NPIX);
        if (tid < 128) {
            us[tid] = ok ? u : 0;
            vs[tid] = ok ? v : 0;
            ue[tid] = ok ? u : -1;
        }
    }
    __syncthreads();

    const __half* xb = g_xsT + (size_t)b * 66 * 66 * CIN;

    // issue chunk gidx into buffer gidx%3 (branch-free staging, zero halo)
    auto issue = [&](int gidx) {
        const int t = gidx >> 3;
        const int ci0 = (gidx & 7) * 64;
        const int iy = (nkx == 2) ? (t >> 1) : t;
        const int ix = t - iy * nkx;
        const int ky = (py == 0) ? iy * 2 : 1;
        const int kx = (px == 0) ? ix * 2 : 1;
        const int dy = (py == 0) ? iy : 0;
        const int dx = (px == 0) ? ix : 0;
        const int bufi = gidx - (gidx / 3) * 3;
        const uint32_t Ab = sb + SM_BUF + bufi * 32768;
        const uint32_t Bb = Ab + 16384;
        const __half* wt = g_wtT + (ky * 3 + kx) * COUT * CIN + ci0;
#pragma unroll
        for (int k = 0; k < 4; k++) {
            int f = tid + k * 256;
            int co = f >> 3, q = f & 7;
            const __half* src = wt + (size_t)(cobase + co) * CIN + q * 8;
            CP_ASYNC16(Ab + sw128(co * 128 + q * 16), src);
        }
#pragma unroll
        for (int k = 0; k < 4; k++) {
            int f = tid + k * 256;
            int j = f >> 3, q = f & 7;
            int y1 = us[j] + 1 - dy, x1 = vs[j] + 1 - dx;
            const __half* src = xb + ((size_t)(y1 * 66 + x1)) * CIN + ci0 + q * 8;
            CP_ASYNC16(Bb + sw128(j * 128 + q * 16), src);
        }
        CP_COMMIT();
    };

    float acc[2][8][4];
#pragma unroll
    for (int mi = 0; mi < 2; mi++)
#pragma unroll
        for (int nt = 0; nt < 8; nt++)
#pragma unroll
            for (int r = 0; r < 4; r++) acc[mi][nt][r] = 0.f;

    issue(0);
    issue(1);

    const int arow = wm * 32 + (lane & 15);
    const int acolb = (lane >> 4) * 16;
    const int brow = wn * 64 + ((lane >> 4) << 3) + (lane & 7);
    const int bcolb = ((lane >> 3) & 1) * 16;

#pragma unroll 1
    for (int c = 0; c < NC; c++) {
        if (c == NC - 1) { CP_WAIT0(); } else { CP_WAIT1(); }
        __syncthreads();
        if (c + 2 < NC) issue(c + 2);
        const int bufi = c - (c / 3) * 3;
        const uint32_t Ab = sb + SM_BUF + bufi * 32768;
        const uint32_t Bb = Ab + 16384;
#pragma unroll
        for (int ks = 0; ks < 4; ks++) {
            uint32_t a[2][4], bb[8][2];
#pragma unroll
            for (int mi = 0; mi < 2; mi++) {
                uint32_t addr = Ab + sw128((arow + mi * 16) * 128 + acolb + ks * 32);
                asm volatile(
                    "ldmatrix.sync.aligned.m8n8.x4.shared.b16 {%0,%1,%2,%3}, [%4];"
                    : "=r"(a[mi][0]), "=r"(a[mi][1]), "=r"(a[mi][2]), "=r"(a[mi][3])
                    : "r"(addr) : "memory");
            }
#pragma unroll
            for (int ntp = 0; ntp < 4; ntp++) {
                uint32_t addr = Bb + sw128((brow + ntp * 16) * 128 + bcolb + ks * 32);
                uint32_t r0, r1, r2, r3;
                asm volatile(
                    "ldmatrix.sync.aligned.m8n8.x4.shared.b16 {%0,%1,%2,%3}, [%4];"
                    : "=r"(r0), "=r"(r1), "=r"(r2), "=r"(r3)
                    : "r"(addr) : "memory");
                bb[ntp * 2][0] = r0;     bb[ntp * 2][1] = r1;
                bb[ntp * 2 + 1][0] = r2; bb[ntp * 2 + 1][1] = r3;
            }
#pragma unroll
            for (int mi = 0; mi < 2; mi++)
#pragma unroll
                for (int nt = 0; nt < 8; nt++) {
                    asm volatile(
                        "mma.sync.aligned.m16n8k16.row.col.f32.f16.f16.f32 "
                        "{%0,%1,%2,%3}, {%4,%5,%6,%7}, {%8,%9}, {%0,%1,%2,%3};"
                        : "+f"(acc[mi][nt][0]), "+f"(acc[mi][nt][1]),
                          "+f"(acc[mi][nt][2]), "+f"(acc[mi][nt][3])
                        : "r"(a[mi][0]), "r"(a[mi][1]), "r"(a[mi][2]),
                          "r"(a[mi][3]), "r"(bb[nt][0]), "r"(bb[nt][1]));
                }
        }
    }

    // Epilogue: demod scale + fp16 parity-plane stores.
    // half2 fast path ONLY when v0 is even (4B-aligned) AND the pair is
    // contiguous in the same row; scalar half stores otherwise.
    __half* plane = g_midp[py * 2 + px];
#pragma unroll
    for (int mi = 0; mi < 2; mi++) {
        int r0 = cobase + wm * 32 + mi * 16 + g;
        float d0 = g_demod[b * COUT + r0];
        float d1 = g_demod[b * COUT + r0 + 8];
        __half* p0 = plane + (size_t)(b * COUT + r0) * 65 * 68;
        __half* p1 = plane + (size_t)(b * COUT + r0 + 8) * 65 * 68;
#pragma unroll
        for (int nt = 0; nt < 8; nt++) {
            int j = wn * 64 + nt * 8 + tg * 2;
            int u0 = ue[j], u1 = ue[j + 1];
            int v0 = vs[j], v1 = vs[j + 1];
            if (u0 >= 0 && u1 == u0 && v1 == v0 + 1 && (v0 & 1) == 0) {
                __half2 h0 = __floats2half2_rn(acc[mi][nt][0] * d0,
                                               acc[mi][nt][1] * d0);
                __half2 h1 = __floats2half2_rn(acc[mi][nt][2] * d1,
                                               acc[mi][nt][3] * d1);
                *reinterpret_cast<__half2*>(p0 + u0 * 68 + v0) = h0;
                *reinterpret_cast<__half2*>(p1 + u0 * 68 + v0) = h1;
            } else {
                if (u0 >= 0) {
                    p0[u0 * 68 + v0] = __float2half_rn(acc[mi][nt][0] * d0);
                    p1[u0 * 68 + v0] = __float2half_rn(acc[mi][nt][2] * d1);
                }
                if (u1 >= 0) {
                    p0[u1 * 68 + v1] = __float2half_rn(acc[mi][nt][1] * d0);
                    p1[u1 * 68 + v1] = __float2half_rn(acc[mi][nt][3] * d1);
                }
            }
        }
    }
}

// ---------------------------------------------------------------------------
// Kernel 6: 4x4 blur from fp16 parity planes -> out [B,COUT,128,128] fp32
// ---------------------------------------------------------------------------
__global__ void k_blur(float* __restrict__ out) {
    int tx0 = blockIdx.x * 32, ty0 = blockIdx.y * 32;
    int bc = blockIdx.z;
    __shared__ float ms[35][36];
    for (int e = threadIdx.x; e < 35 * 35; e += 256) {
        int r = e / 35, c = e - r * 35;
        int my = ty0 - 1 + r, mx = tx0 - 1 + c;
        float v = 0.f;
        if (my >= 0 && my < 129 && mx >= 0 && mx < 129)
            v = __half2float(g_midp[(my & 1) * 2 + (mx & 1)]
                                   [((size_t)bc * 65 + (my >> 1)) * 68 + (mx >> 1)]);
        ms[r][c] = v;
    }
    __syncthreads();
    int fx = threadIdx.x & 31;
    int q = (threadIdx.x >> 5) * 4;
    float cs[7];
#pragma unroll
    for (int m = 0; m < 7; m++) {
        float* row = ms[q + m];
        cs[m] = row[fx] + 3.f * row[fx + 1] + 3.f * row[fx + 2] + row[fx + 3];
    }
    float* op = out + ((size_t)bc * 128 + ty0 + q) * 128 + tx0 + fx;
#pragma unroll
    for (int j = 0; j < 4; j++) {
        float s = cs[j] + 3.f * cs[j + 1] + 3.f * cs[j + 2] + cs[j + 3];
        op[j * 128] = s * (1.f / 16.f);
    }
}

// ---------------------------------------------------------------------------
extern "C" void kernel_launch(void* const* d_in, const int* in_sizes, int n_in,
                              void* d_out, int out_size) {
    const float* input  = (const float*)d_in[0];
    const float* style  = (const float*)d_in[1];
    const float* weight = (const float*)d_in[2];
    const float* modw   = (const float*)d_in[3];
    const float* modb   = (const float*)d_in[4];
    float* out = (float*)d_out;

    cudaFuncSetAttribute(k_conv, cudaFuncAttributeMaxDynamicSharedMemorySize, SM_DYN);

    k_style<<<B, CIN>>>(style, modw, modb);
    k_wtT<<<COUT, 256>>>(weight);
    k_halo<<<dim3(260, B), 256>>>();
    k_xsT<<<dim3(H, B), 256>>>(input);
    k_demod<<<COUT, 256>>>(weight);

    k_conv<<<dim3(132, 2, B), 256, SM_DYN>>>();

    k_blur<<<dim3(4, 4, B * COUT), 256>>>(out);
}